// round 1
// baseline (speedup 1.0000x reference)
#include <cuda_runtime.h>

// Problem constants
#define TOK  4096          // B*S tokens
#define DIM  1024          // D
#define NE   8             // experts
#define DFFC 4096          // DFF

// GEMM tiling
#define BM 128
#define BN 64
#define BK 16
#define CAP 9216           // 2*TOK + NE*BM worst-case aligned rows
#define MT  (CAP/BM)       // 72 m-tiles max
#define ASTR (BM+4)        // 132 (mult of 4 -> float4-aligned rows)
#define BSTR (BN+4)        // 68

// ---------------- device scratch (no allocations allowed) ----------------
__device__ int   g_cnt[NE];
__device__ int   g_fill[NE];
__device__ int   g_off[NE];
__device__ int   g_rows[NE];
__device__ int   g_eid[TOK*2];
__device__ float g_ew[TOK*2];
__device__ int   g_perm[CAP];
__device__ float g_pw[CAP];
__device__ float g_H[(size_t)CAP*DFFC];   // ~151 MB hidden activations

// ---------------- setup kernels ----------------
__global__ void k_init() {
    int i = threadIdx.x;
    if (i < NE) { g_cnt[i] = 0; g_fill[i] = 0; }
}

// One warp per token: logits, top-2, softmax-over-2, histogram.
__global__ void k_router(const float* __restrict__ x,
                         const float* __restrict__ Wg,
                         const float* __restrict__ bg) {
    int warp = threadIdx.x >> 5, lane = threadIdx.x & 31;
    int t = blockIdx.x * 4 + warp;
    const float* xr = x + (size_t)t * DIM;
    float acc[NE];
#pragma unroll
    for (int e = 0; e < NE; e++) acc[e] = 0.f;
    for (int k = lane; k < DIM; k += 32) {
        float xv = xr[k];
#pragma unroll
        for (int e = 0; e < NE; e++) acc[e] += xv * Wg[e * DIM + k];
    }
#pragma unroll
    for (int e = 0; e < NE; e++) {
#pragma unroll
        for (int o = 16; o > 0; o >>= 1)
            acc[e] += __shfl_xor_sync(0xffffffffu, acc[e], o);
    }
    if (lane == 0) {
        float v0 = -1e30f, v1 = -1e30f; int i0 = 0, i1 = 0;
#pragma unroll
        for (int e = 0; e < NE; e++) {
            float v = acc[e] + bg[e];
            if (v > v0)      { v1 = v0; i1 = i0; v0 = v; i0 = e; }
            else if (v > v1) { v1 = v;  i1 = e; }
        }
        // softmax over the two surviving logits (others are exactly 0 weight)
        float e1 = __expf(v1 - v0);
        float w0 = 1.f / (1.f + e1);
        float w1 = e1 * w0;
        g_eid[2*t] = i0; g_eid[2*t+1] = i1;
        g_ew [2*t] = w0; g_ew [2*t+1] = w1;
        atomicAdd(&g_cnt[i0], 1);
        atomicAdd(&g_cnt[i1], 1);
    }
}

__global__ void k_offsets() {
    if (threadIdx.x == 0) {
        int acc = 0;
        for (int e = 0; e < NE; e++) {
            g_off[e]  = acc;
            g_rows[e] = g_cnt[e];
            acc += ((g_cnt[e] + BM - 1) / BM) * BM;   // BM-aligned buckets
        }
    }
}

__global__ void k_scatter() {
    int t = blockIdx.x * blockDim.x + threadIdx.x;
    if (t >= TOK) return;
#pragma unroll
    for (int s = 0; s < 2; s++) {
        int e = g_eid[2*t + s];
        int pos = g_off[e] + atomicAdd(&g_fill[e], 1);
        g_perm[pos] = t;
        g_pw[pos]   = g_ew[2*t + s];
    }
}

__global__ void k_zero(float* __restrict__ y) {
    size_t i = (size_t)blockIdx.x * blockDim.x + threadIdx.x;
    if (i < (size_t)TOK * DIM) y[i] = 0.f;
}

// Map a global m-tile index to (expert, absolute row base, absolute row bound).
__device__ __forceinline__ bool find_expert(int mt, int& e, int& m0, int& ne) {
    e = -1;
#pragma unroll
    for (int i = 0; i < NE; i++) {
        int o = g_off[i], r = g_rows[i];
        int t0 = o / BM, tl = (r + BM - 1) / BM;
        if (mt >= t0 && mt < t0 + tl) { e = i; m0 = o + (mt - t0) * BM; ne = o + r; }
    }
    return e >= 0;
}

// ---------------- GEMM 1+3 fused: H = silu(Xg @ W1^T) * (Xg @ W3^T) ----------------
__global__ void __launch_bounds__(256, 2)
k_gemm13(const float* __restrict__ x,
         const float* __restrict__ W1,
         const float* __restrict__ W3) {
    __shared__ float As [BK * ASTR];
    __shared__ float B1s[BK * BSTR];
    __shared__ float B3s[BK * BSTR];
    __shared__ int   srow[BM];

    int e, m0, ne;
    if (!find_expert(blockIdx.y, e, m0, ne)) return;

    int tid = threadIdx.x;
    if (tid < BM) {
        int pos = m0 + tid;
        srow[tid] = (pos < ne) ? g_perm[pos] : 0;   // clamp keeps loads in-bounds
    }
    __syncthreads();

    int n0 = blockIdx.x * BN;
    const float* B1g = W1 + ((size_t)e * DFFC + n0) * DIM;
    const float* B3g = W3 + ((size_t)e * DFFC + n0) * DIM;

    int tx = tid & 15, ty = tid >> 4;
    float acc1[8][4], acc3[8][4];
#pragma unroll
    for (int i = 0; i < 8; i++)
#pragma unroll
        for (int j = 0; j < 4; j++) { acc1[i][j] = 0.f; acc3[i][j] = 0.f; }

    for (int k0 = 0; k0 < DIM; k0 += BK) {
        // A tile: 128x16, 2 float4 per thread, stored transposed [k][m]
#pragma unroll
        for (int l = 0; l < 2; l++) {
            int lin = tid + l * 256;
            int ar = lin >> 2, kq = lin & 3;
            float4 v = *reinterpret_cast<const float4*>(
                x + (size_t)srow[ar] * DIM + k0 + kq * 4);
            As[(kq*4+0)*ASTR + ar] = v.x;
            As[(kq*4+1)*ASTR + ar] = v.y;
            As[(kq*4+2)*ASTR + ar] = v.z;
            As[(kq*4+3)*ASTR + ar] = v.w;
        }
        // B tiles: 64x16 each, 1 float4 per thread
        {
            int br = tid >> 2, kq = tid & 3;
            float4 v1 = *reinterpret_cast<const float4*>(B1g + (size_t)br * DIM + k0 + kq * 4);
            float4 v3 = *reinterpret_cast<const float4*>(B3g + (size_t)br * DIM + k0 + kq * 4);
            B1s[(kq*4+0)*BSTR + br] = v1.x;
            B1s[(kq*4+1)*BSTR + br] = v1.y;
            B1s[(kq*4+2)*BSTR + br] = v1.z;
            B1s[(kq*4+3)*BSTR + br] = v1.w;
            B3s[(kq*4+0)*BSTR + br] = v3.x;
            B3s[(kq*4+1)*BSTR + br] = v3.y;
            B3s[(kq*4+2)*BSTR + br] = v3.z;
            B3s[(kq*4+3)*BSTR + br] = v3.w;
        }
        __syncthreads();
#pragma unroll
        for (int kk = 0; kk < BK; kk++) {
            const float4* ap = reinterpret_cast<const float4*>(&As[kk * ASTR + ty * 8]);
            float4 a0 = ap[0], a1 = ap[1];
            float4 b1 = *reinterpret_cast<const float4*>(&B1s[kk * BSTR + tx * 4]);
            float4 b3 = *reinterpret_cast<const float4*>(&B3s[kk * BSTR + tx * 4]);
            float a[8]  = {a0.x, a0.y, a0.z, a0.w, a1.x, a1.y, a1.z, a1.w};
            float c1[4] = {b1.x, b1.y, b1.z, b1.w};
            float c3[4] = {b3.x, b3.y, b3.z, b3.w};
#pragma unroll
            for (int i = 0; i < 8; i++)
#pragma unroll
                for (int j = 0; j < 4; j++) {
                    acc1[i][j] += a[i] * c1[j];
                    acc3[i][j] += a[i] * c3[j];
                }
        }
        __syncthreads();
    }

    // epilogue: h = silu(acc1) * acc3
#pragma unroll
    for (int i = 0; i < 8; i++) {
        int pos = m0 + ty * 8 + i;
        if (pos < ne) {
            float* hr = g_H + (size_t)pos * DFFC + n0 + tx * 4;
#pragma unroll
            for (int j = 0; j < 4; j++) {
                float z = acc1[i][j];
                float s = z / (1.f + __expf(-z));
                hr[j] = s * acc3[i][j];
            }
        }
    }
}

// ---------------- GEMM 2: y[t] += w * (H @ W2^T) ----------------
__global__ void __launch_bounds__(256, 2)
k_gemm2(const float* __restrict__ W2, float* __restrict__ y) {
    __shared__ float As[BK * ASTR];
    __shared__ float Bs[BK * BSTR];

    int e, m0, ne;
    if (!find_expert(blockIdx.y, e, m0, ne)) return;

    int tid = threadIdx.x;
    int n0 = blockIdx.x * BN;
    const float* Bg = W2 + ((size_t)e * DIM + n0) * DFFC;

    int tx = tid & 15, ty = tid >> 4;
    float acc[8][4];
#pragma unroll
    for (int i = 0; i < 8; i++)
#pragma unroll
        for (int j = 0; j < 4; j++) acc[i][j] = 0.f;

    for (int k0 = 0; k0 < DFFC; k0 += BK) {
#pragma unroll
        for (int l = 0; l < 2; l++) {
            int lin = tid + l * 256;
            int ar = lin >> 2, kq = lin & 3;
            float4 v = *reinterpret_cast<const float4*>(
                g_H + (size_t)(m0 + ar) * DFFC + k0 + kq * 4);
            As[(kq*4+0)*ASTR + ar] = v.x;
            As[(kq*4+1)*ASTR + ar] = v.y;
            As[(kq*4+2)*ASTR + ar] = v.z;
            As[(kq*4+3)*ASTR + ar] = v.w;
        }
        {
            int br = tid >> 2, kq = tid & 3;
            float4 v = *reinterpret_cast<const float4*>(Bg + (size_t)br * DFFC + k0 + kq * 4);
            Bs[(kq*4+0)*BSTR + br] = v.x;
            Bs[(kq*4+1)*BSTR + br] = v.y;
            Bs[(kq*4+2)*BSTR + br] = v.z;
            Bs[(kq*4+3)*BSTR + br] = v.w;
        }
        __syncthreads();
#pragma unroll
        for (int kk = 0; kk < BK; kk++) {
            const float4* ap = reinterpret_cast<const float4*>(&As[kk * ASTR + ty * 8]);
            float4 a0 = ap[0], a1 = ap[1];
            float4 b  = *reinterpret_cast<const float4*>(&Bs[kk * BSTR + tx * 4]);
            float a[8] = {a0.x, a0.y, a0.z, a0.w, a1.x, a1.y, a1.z, a1.w};
            float c[4] = {b.x, b.y, b.z, b.w};
#pragma unroll
            for (int i = 0; i < 8; i++)
#pragma unroll
                for (int j = 0; j < 4; j++) acc[i][j] += a[i] * c[j];
        }
        __syncthreads();
    }

    // epilogue: weighted scatter-add into output (2 commutative adds/token -> deterministic)
#pragma unroll
    for (int i = 0; i < 8; i++) {
        int pos = m0 + ty * 8 + i;
        if (pos < ne) {
            int   t = g_perm[pos];
            float w = g_pw[pos];
            float* yr = y + (size_t)t * DIM + n0 + tx * 4;
#pragma unroll
            for (int j = 0; j < 4; j++) atomicAdd(&yr[j], w * acc[i][j]);
        }
    }
}

// ---------------- launch ----------------
extern "C" void kernel_launch(void* const* d_in, const int* in_sizes, int n_in,
                              void* d_out, int out_size) {
    const float* x  = (const float*)d_in[0];
    const float* Wg = (const float*)d_in[1];
    const float* bg = (const float*)d_in[2];
    const float* W1 = (const float*)d_in[3];
    const float* W2 = (const float*)d_in[4];
    const float* W3 = (const float*)d_in[5];
    float* y = (float*)d_out;

    k_init<<<1, 32>>>();
    k_router<<<TOK / 4, 128>>>(x, Wg, bg);
    k_offsets<<<1, 1>>>();
    k_scatter<<<TOK / 256, 256>>>();
    k_zero<<<(TOK * DIM) / 256, 256>>>(y);
    dim3 g13(DFFC / BN, MT);
    k_gemm13<<<g13, 256>>>(x, W1, W3);
    dim3 g2(DIM / BN, MT);
    k_gemm2<<<g2, 256>>>(W2, y);
}

// round 3
// speedup vs baseline: 3.0195x; 3.0195x over previous
#include <cuda_runtime.h>
#include <cstdint>

// Problem constants
#define TOK  4096
#define DIM  1024
#define NE   8
#define DFFC 4096

#define BM   128
#define BK   16
#define CAP  9216
#define MT   (CAP/BM)
#define SSTR 20            // floats per smem row (64B data + 16B pad) -> conflict-free ldmatrix

// ---------------- device scratch ----------------
__device__ int   g_cnt[NE];
__device__ int   g_fill[NE];
__device__ int   g_off[NE];
__device__ int   g_rows[NE];
__device__ int   g_eid[TOK*2];
__device__ float g_ew[TOK*2];
__device__ int   g_perm[CAP];
__device__ float g_pw[CAP];
__device__ float g_X[(size_t)CAP*DIM];    // gathered, tf32(RN)-rounded activations
__device__ float g_H[(size_t)CAP*DFFC];   // hidden acts, tf32(RN)-rounded

// ---------------- PTX helpers ----------------
__device__ __forceinline__ uint32_t smem_u32(const void* p) {
    uint32_t a;
    asm("{ .reg .u64 t; cvta.to.shared.u64 t, %1; cvt.u32.u64 %0, t; }" : "=r"(a) : "l"(p));
    return a;
}

#define CPA(s, g)   asm volatile("cp.async.cg.shared.global [%0], [%1], 16;" :: "r"(s), "l"(g) : "memory")
#define CPCOMMIT()  asm volatile("cp.async.commit_group;" ::: "memory")
#define CPWAIT(n)   asm volatile("cp.async.wait_group %0;" :: "n"(n) : "memory")

#define LDSM4(r, a) asm volatile("ldmatrix.sync.aligned.m8n8.x4.shared.b16 {%0,%1,%2,%3}, [%4];" \
    : "=r"((r)[0]), "=r"((r)[1]), "=r"((r)[2]), "=r"((r)[3]) : "r"(a))

// c += a * b  (m16n8k8 tf32, fp32 accumulate)
#define MMA(c, a, b0, b1) asm volatile( \
    "mma.sync.aligned.m16n8k8.row.col.f32.tf32.tf32.f32 " \
    "{%0,%1,%2,%3},{%4,%5,%6,%7},{%8,%9},{%0,%1,%2,%3};" \
    : "+f"((c)[0]), "+f"((c)[1]), "+f"((c)[2]), "+f"((c)[3]) \
    : "r"((a)[0]), "r"((a)[1]), "r"((a)[2]), "r"((a)[3]), "r"(b0), "r"(b1))

#define CVT_TF32(x) asm("cvt.rna.tf32.f32 %0, %0;" : "+r"(x))

__device__ __forceinline__ float rtf(float x) {
    uint32_t r;
    asm("cvt.rna.tf32.f32 %0, %1;" : "=r"(r) : "f"(x));
    return __uint_as_float(r);
}
__device__ __forceinline__ float4 rtf4(float4 v) {
    v.x = rtf(v.x); v.y = rtf(v.y); v.z = rtf(v.z); v.w = rtf(v.w);
    return v;
}

// ---------------- setup kernels ----------------
__global__ void k_init() {
    int i = threadIdx.x;
    if (i < NE) { g_cnt[i] = 0; g_fill[i] = 0; }
}

__global__ void k_router(const float* __restrict__ x,
                         const float* __restrict__ Wg,
                         const float* __restrict__ bg) {
    int warp = threadIdx.x >> 5, lane = threadIdx.x & 31;
    int t = blockIdx.x * 4 + warp;
    const float* xr = x + (size_t)t * DIM;
    float acc[NE];
#pragma unroll
    for (int e = 0; e < NE; e++) acc[e] = 0.f;
    for (int k = lane; k < DIM; k += 32) {
        float xv = xr[k];
#pragma unroll
        for (int e = 0; e < NE; e++) acc[e] += xv * Wg[e * DIM + k];
    }
#pragma unroll
    for (int e = 0; e < NE; e++)
#pragma unroll
        for (int o = 16; o > 0; o >>= 1)
            acc[e] += __shfl_xor_sync(0xffffffffu, acc[e], o);
    if (lane == 0) {
        float v0 = -1e30f, v1 = -1e30f; int i0 = 0, i1 = 0;
#pragma unroll
        for (int e = 0; e < NE; e++) {
            float v = acc[e] + bg[e];
            if (v > v0)      { v1 = v0; i1 = i0; v0 = v; i0 = e; }
            else if (v > v1) { v1 = v;  i1 = e; }
        }
        float e1 = __expf(v1 - v0);
        float w0 = 1.f / (1.f + e1);
        float w1 = e1 * w0;
        g_eid[2*t] = i0; g_eid[2*t+1] = i1;
        g_ew [2*t] = w0; g_ew [2*t+1] = w1;
        atomicAdd(&g_cnt[i0], 1);
        atomicAdd(&g_cnt[i1], 1);
    }
}

__global__ void k_offsets() {
    if (threadIdx.x == 0) {
        int acc = 0;
        for (int e = 0; e < NE; e++) {
            g_off[e]  = acc;
            g_rows[e] = g_cnt[e];
            acc += ((g_cnt[e] + BM - 1) / BM) * BM;
        }
    }
}

__global__ void k_scatter() {
    int t = blockIdx.x * blockDim.x + threadIdx.x;
    if (t >= TOK) return;
#pragma unroll
    for (int s = 0; s < 2; s++) {
        int e = g_eid[2*t + s];
        int pos = g_off[e] + atomicAdd(&g_fill[e], 1);
        g_perm[pos] = t;
        g_pw[pos]   = g_ew[2*t + s];
    }
}

__global__ void k_gather(const float* __restrict__ x) {
    int pos = blockIdx.x;
    bool valid = false;
#pragma unroll
    for (int e = 0; e < NE; e++)
        valid |= (pos >= g_off[e] && pos < g_off[e] + g_rows[e]);
    float4 v = make_float4(0.f, 0.f, 0.f, 0.f);
    if (valid) {
        int t = g_perm[pos];
        v = rtf4(*reinterpret_cast<const float4*>(x + (size_t)t * DIM + threadIdx.x * 4));
    }
    *reinterpret_cast<float4*>(g_X + (size_t)pos * DIM + threadIdx.x * 4) = v;
}

__global__ void k_zero(float4* __restrict__ y) {
    y[blockIdx.x * 256 + threadIdx.x] = make_float4(0.f, 0.f, 0.f, 0.f);
}

__device__ __forceinline__ bool find_expert(int mt, int& e, int& m0, int& ne) {
    e = -1;
#pragma unroll
    for (int i = 0; i < NE; i++) {
        int o = g_off[i], r = g_rows[i];
        int t0 = o / BM, tl = (r + BM - 1) / BM;
        if (mt >= t0 && mt < t0 + tl) { e = i; m0 = o + (mt - t0) * BM; ne = o + r; }
    }
    return e >= 0;
}

// =============== GEMM 1+3 fused: H = silu(X@W1^T)*(X@W3^T), tf32 mma.sync ===============
// CTA tile 128x64, BK=16, 8 warps (2m x 4n), warp tile 64x16, dual accumulators.
__global__ void __launch_bounds__(256)
k_gemm13(const float* __restrict__ W1, const float* __restrict__ W3) {
    __shared__ float sA [2][BM * SSTR];
    __shared__ float sB1[2][64 * SSTR];
    __shared__ float sB3[2][64 * SSTR];

    int e, m0, ne_;
    if (!find_expert((int)blockIdx.x, e, m0, ne_)) return;

    const int tid = threadIdx.x, lane = tid & 31, wid = tid >> 5;
    const int wm = wid & 1, wn = wid >> 1;
    const int n0 = blockIdx.y * 64;

    const float* Ag  = g_X + (size_t)m0 * DIM;
    const float* B1g = W1 + ((size_t)e * DFFC + n0) * DIM;
    const float* B3g = W3 + ((size_t)e * DFFC + n0) * DIM;

    const uint32_t sA0  = smem_u32(sA);
    const uint32_t sB10 = smem_u32(sB1);
    const uint32_t sB30 = smem_u32(sB3);
    const uint32_t stA = BM * SSTR * 4, stB = 64 * SSTR * 4;

    // cp.async mapping
    const int ar0 = tid >> 2, aq = tid & 3;          // A: 2 chunks/thread
    const int br  = tid >> 2, bq = tid & 3;          // B: 1 chunk/thread each

#define G13_LOAD(s, k0) do {                                                  \
    _Pragma("unroll")                                                         \
    for (int l = 0; l < 2; l++) {                                             \
        int r = ar0 + l * 64;                                                 \
        CPA(sA0 + (s)*stA + (r*SSTR + aq*4)*4, Ag + (size_t)r*DIM + (k0) + aq*4); \
    }                                                                         \
    CPA(sB10 + (s)*stB + (br*SSTR + bq*4)*4, B1g + (size_t)br*DIM + (k0) + bq*4); \
    CPA(sB30 + (s)*stB + (br*SSTR + bq*4)*4, B3g + (size_t)br*DIM + (k0) + bq*4); \
    CPCOMMIT();                                                               \
} while (0)

    // fragment ldmatrix addresses (within stage 0)
    const uint32_t aAddr0 = sA0 + (((wm*64 + (lane & 15)) * SSTR + (lane >> 4) * 4)) * 4;
    const uint32_t bRowOff = ((wn*16 + (lane & 7)) * SSTR + ((lane >> 3) & 3) * 4) * 4;
    const uint32_t b1Addr0 = sB10 + bRowOff;
    const uint32_t b3Addr0 = sB30 + bRowOff;

    float c1[4][2][4], c3[4][2][4];
#pragma unroll
    for (int i = 0; i < 4; i++)
#pragma unroll
        for (int j = 0; j < 2; j++)
#pragma unroll
            for (int q = 0; q < 4; q++) { c1[i][j][q] = 0.f; c3[i][j][q] = 0.f; }

    const int NS = DIM / BK;   // 64
    G13_LOAD(0, 0);

    for (int i = 0; i < NS; i++) {
        int s = i & 1;
        if (i + 1 < NS) { G13_LOAD(1 - s, (i + 1) * BK); CPWAIT(1); }
        else            { CPWAIT(0); }
        __syncthreads();

        // B fragments (x4 covers both k-steps), cvt weights to tf32 (RN)
        uint32_t b1f[2][4], b3f[2][4];
#pragma unroll
        for (int nt = 0; nt < 2; nt++) {
            LDSM4(b1f[nt], b1Addr0 + s*stB + nt*8*SSTR*4);
            LDSM4(b3f[nt], b3Addr0 + s*stB + nt*8*SSTR*4);
#pragma unroll
            for (int q = 0; q < 4; q++) { CVT_TF32(b1f[nt][q]); CVT_TF32(b3f[nt][q]); }
        }
#pragma unroll
        for (int ks = 0; ks < 2; ks++) {
#pragma unroll
            for (int mt = 0; mt < 4; mt++) {
                uint32_t a[4];
                LDSM4(a, aAddr0 + s*stA + mt*16*SSTR*4 + ks*32);
#pragma unroll
                for (int nt = 0; nt < 2; nt++) {
                    MMA(c1[mt][nt], a, b1f[nt][ks*2], b1f[nt][ks*2+1]);
                    MMA(c3[mt][nt], a, b3f[nt][ks*2], b3f[nt][ks*2+1]);
                }
            }
        }
        __syncthreads();
    }

    // epilogue: silu(c1)*c3 -> tf32 round -> g_H
#pragma unroll
    for (int mt = 0; mt < 4; mt++)
#pragma unroll
        for (int nt = 0; nt < 2; nt++) {
            int row = m0 + wm*64 + mt*16 + (lane >> 2);
            int col = n0 + wn*16 + nt*8 + (lane & 3) * 2;
#pragma unroll
            for (int h = 0; h < 2; h++) {
                int r = row + h * 8;
                if (r < ne_) {
                    float z0 = c1[mt][nt][h*2],   g0 = z0 / (1.f + __expf(-z0)) * c3[mt][nt][h*2];
                    float z1 = c1[mt][nt][h*2+1], g1 = z1 / (1.f + __expf(-z1)) * c3[mt][nt][h*2+1];
                    float2 v = make_float2(rtf(g0), rtf(g1));
                    *reinterpret_cast<float2*>(g_H + (size_t)r * DFFC + col) = v;
                }
            }
        }
}

// =============== GEMM 2: y += w * (H @ W2^T), tf32 mma.sync ===============
// CTA tile 128x128, BK=16, 8 warps (2m x 4n), warp tile 64x32.
__global__ void __launch_bounds__(256)
k_gemm2(const float* __restrict__ W2, float* __restrict__ y) {
    __shared__ float sA[2][BM * SSTR];
    __shared__ float sB[2][128 * SSTR];
    __shared__ int   srow[BM];
    __shared__ float swt[BM];

    int e, m0, ne_;
    if (!find_expert((int)blockIdx.y, e, m0, ne_)) return;

    const int tid = threadIdx.x, lane = tid & 31, wid = tid >> 5;
    const int wm = wid & 1, wn = wid >> 1;
    const int n0 = blockIdx.x * 128;

    if (tid < BM) {
        int pos = m0 + tid;
        bool v = pos < ne_;
        srow[tid] = v ? g_perm[pos] : -1;
        swt[tid]  = v ? g_pw[pos]   : 0.f;
    }

    const float* Ag = g_H + (size_t)m0 * DFFC;
    const float* Bg = W2 + ((size_t)e * DIM + n0) * DFFC;

    const uint32_t sA0 = smem_u32(sA);
    const uint32_t sB0 = smem_u32(sB);
    const uint32_t stA = BM * SSTR * 4, stB = 128 * SSTR * 4;

    const int r0 = tid >> 2, q = tid & 3;

#define G2_LOAD(s, k0) do {                                                   \
    _Pragma("unroll")                                                         \
    for (int l = 0; l < 2; l++) {                                             \
        int r = r0 + l * 64;                                                  \
        CPA(sA0 + (s)*stA + (r*SSTR + q*4)*4, Ag + (size_t)r*DFFC + (k0) + q*4); \
        CPA(sB0 + (s)*stB + (r*SSTR + q*4)*4, Bg + (size_t)r*DFFC + (k0) + q*4); \
    }                                                                         \
    CPCOMMIT();                                                               \
} while (0)

    const uint32_t aAddr0 = sA0 + (((wm*64 + (lane & 15)) * SSTR + (lane >> 4) * 4)) * 4;
    const uint32_t bAddr0 = sB0 + (((wn*32 + (lane & 7)) * SSTR + ((lane >> 3) & 3) * 4)) * 4;

    float c[4][4][4];
#pragma unroll
    for (int i = 0; i < 4; i++)
#pragma unroll
        for (int j = 0; j < 4; j++)
#pragma unroll
            for (int k = 0; k < 4; k++) c[i][j][k] = 0.f;

    const int NS = DFFC / BK;   // 256
    G2_LOAD(0, 0);

    for (int i = 0; i < NS; i++) {
        int s = i & 1;
        if (i + 1 < NS) { G2_LOAD(1 - s, (i + 1) * BK); CPWAIT(1); }
        else            { CPWAIT(0); }
        __syncthreads();

        uint32_t bf[4][4];
#pragma unroll
        for (int nt = 0; nt < 4; nt++) {
            LDSM4(bf[nt], bAddr0 + s*stB + nt*8*SSTR*4);
#pragma unroll
            for (int qq = 0; qq < 4; qq++) CVT_TF32(bf[nt][qq]);
        }
#pragma unroll
        for (int ks = 0; ks < 2; ks++) {
#pragma unroll
            for (int mt = 0; mt < 4; mt++) {
                uint32_t a[4];
                LDSM4(a, aAddr0 + s*stA + mt*16*SSTR*4 + ks*32);
#pragma unroll
                for (int nt = 0; nt < 4; nt++)
                    MMA(c[mt][nt], a, bf[nt][ks*2], bf[nt][ks*2+1]);
            }
        }
        __syncthreads();
    }

    // epilogue: weighted scatter-add (2 commutative fp32 adds per output element)
#pragma unroll
    for (int mt = 0; mt < 4; mt++) {
        int rl = wm*64 + mt*16 + (lane >> 2);
#pragma unroll
        for (int h = 0; h < 2; h++) {
            int r = rl + h * 8;
            int t = srow[r];
            if (t >= 0) {
                float w = swt[r];
                float* yr = y + (size_t)t * DIM + n0 + wn*32 + (lane & 3) * 2;
#pragma unroll
                for (int nt = 0; nt < 4; nt++) {
                    atomicAdd(&yr[nt*8],     w * c[mt][nt][h*2]);
                    atomicAdd(&yr[nt*8 + 1], w * c[mt][nt][h*2+1]);
                }
            }
        }
    }
}

// ---------------- launch ----------------
extern "C" void kernel_launch(void* const* d_in, const int* in_sizes, int n_in,
                              void* d_out, int out_size) {
    const float* x  = (const float*)d_in[0];
    const float* Wg = (const float*)d_in[1];
    const float* bg = (const float*)d_in[2];
    const float* W1 = (const float*)d_in[3];
    const float* W2 = (const float*)d_in[4];
    const float* W3 = (const float*)d_in[5];
    float* y = (float*)d_out;

    k_init<<<1, 32>>>();
    k_router<<<TOK / 4, 128>>>(x, Wg, bg);
    k_offsets<<<1, 1>>>();
    k_scatter<<<TOK / 256, 256>>>();
    k_gather<<<CAP, 256>>>(x);
    k_zero<<<(TOK * DIM) / 1024, 256>>>((float4*)y);

    dim3 g13(MT, DFFC / 64);         // x = m-tiles fast: W1/W3 panel reuse in L2, g_X resident
    k_gemm13<<<g13, 256>>>(W1, W3);
    dim3 g2(DIM / 128, MT);          // x = n (8): g_H tile reuse across n in each wave
    k_gemm2<<<g2, 256>>>(W2, y);
}

// round 5
// speedup vs baseline: 5.5581x; 1.8407x over previous
#include <cuda_runtime.h>
#include <cuda_fp16.h>
#include <cstdint>

// Problem constants
#define TOK  4096
#define DIM  1024
#define NE   8
#define DFFC 4096

#define BM   128
#define BK   32
#define CAP  9216
#define MT   (CAP/BM)
#define HSTR 40            // halfs per smem row (64B data + 16B pad), ldmatrix conflict-free

// ---------------- device scratch ----------------
__device__ int    g_cnt[NE];
__device__ int    g_fill[NE];
__device__ int    g_off[NE];
__device__ int    g_rows[NE];
__device__ int    g_eid[TOK*2];
__device__ float  g_ew[TOK*2];
__device__ int    g_perm[CAP];
__device__ float  g_pw[CAP];
__device__ __half g_X[(size_t)CAP*DIM];     // gathered fp16 activations (pads = 0)
__device__ __half g_H[(size_t)CAP*DFFC];    // fp16 hidden activations
__device__ __half g_W1h[(size_t)NE*DFFC*DIM];
__device__ __half g_W3h[(size_t)NE*DFFC*DIM];
__device__ __half g_W2h[(size_t)NE*DIM*DFFC];

// ---------------- PTX helpers ----------------
__device__ __forceinline__ uint32_t smem_u32(const void* p) {
    uint32_t a;
    asm("{ .reg .u64 t; cvta.to.shared.u64 t, %1; cvt.u32.u64 %0, t; }" : "=r"(a) : "l"(p));
    return a;
}

#define CPA(s, g)   asm volatile("cp.async.cg.shared.global [%0], [%1], 16;" :: "r"(s), "l"(g) : "memory")
#define CPCOMMIT()  asm volatile("cp.async.commit_group;" ::: "memory")
#define CPWAIT(n)   asm volatile("cp.async.wait_group %0;" :: "n"(n) : "memory")

#define LDSM4(r, a) asm volatile("ldmatrix.sync.aligned.m8n8.x4.shared.b16 {%0,%1,%2,%3}, [%4];" \
    : "=r"((r)[0]), "=r"((r)[1]), "=r"((r)[2]), "=r"((r)[3]) : "r"(a))

// c += a*b   (m16n8k16 fp16 in, fp32 accumulate)
#define MMAH(c, a, b0, b1) asm volatile( \
    "mma.sync.aligned.m16n8k16.row.col.f32.f16.f16.f32 " \
    "{%0,%1,%2,%3},{%4,%5,%6,%7},{%8,%9},{%0,%1,%2,%3};" \
    : "+f"((c)[0]), "+f"((c)[1]), "+f"((c)[2]), "+f"((c)[3]) \
    : "r"((a)[0]), "r"((a)[1]), "r"((a)[2]), "r"((a)[3]), "r"(b0), "r"(b1))

// ---------------- setup kernels ----------------
__global__ void k_init() {
    int i = threadIdx.x;
    if (i < NE) { g_cnt[i] = 0; g_fill[i] = 0; }
}

__global__ void k_router(const float* __restrict__ x,
                         const float* __restrict__ Wg,
                         const float* __restrict__ bg) {
    int warp = threadIdx.x >> 5, lane = threadIdx.x & 31;
    int t = blockIdx.x * 4 + warp;
    const float* xr = x + (size_t)t * DIM;
    float acc[NE];
#pragma unroll
    for (int e = 0; e < NE; e++) acc[e] = 0.f;
    for (int k = lane; k < DIM; k += 32) {
        float xv = xr[k];
#pragma unroll
        for (int e = 0; e < NE; e++) acc[e] += xv * Wg[e * DIM + k];
    }
#pragma unroll
    for (int e = 0; e < NE; e++)
#pragma unroll
        for (int o = 16; o > 0; o >>= 1)
            acc[e] += __shfl_xor_sync(0xffffffffu, acc[e], o);
    if (lane == 0) {
        float v0 = -1e30f, v1 = -1e30f; int i0 = 0, i1 = 0;
#pragma unroll
        for (int e = 0; e < NE; e++) {
            float v = acc[e] + bg[e];
            if (v > v0)      { v1 = v0; i1 = i0; v0 = v; i0 = e; }
            else if (v > v1) { v1 = v;  i1 = e; }
        }
        float e1 = __expf(v1 - v0);
        float w0 = 1.f / (1.f + e1);
        float w1 = e1 * w0;
        g_eid[2*t] = i0; g_eid[2*t+1] = i1;
        g_ew [2*t] = w0; g_ew [2*t+1] = w1;
        atomicAdd(&g_cnt[i0], 1);
        atomicAdd(&g_cnt[i1], 1);
    }
}

__global__ void k_offsets() {
    if (threadIdx.x == 0) {
        int acc = 0;
        for (int e = 0; e < NE; e++) {
            g_off[e]  = acc;
            g_rows[e] = g_cnt[e];
            acc += ((g_cnt[e] + BM - 1) / BM) * BM;
        }
    }
}

__global__ void k_scatter() {
    int t = blockIdx.x * blockDim.x + threadIdx.x;
    if (t >= TOK) return;
#pragma unroll
    for (int s = 0; s < 2; s++) {
        int e = g_eid[2*t + s];
        int pos = g_off[e] + atomicAdd(&g_fill[e], 1);
        g_perm[pos] = t;
        g_pw[pos]   = g_ew[2*t + s];
    }
}

// Gather tokens into per-expert buckets as fp16 (RN); zero the pad rows.
__global__ void k_gather(const float* __restrict__ x) {
    int pos = blockIdx.x;
    bool valid = false;
#pragma unroll
    for (int e = 0; e < NE; e++)
        valid |= (pos >= g_off[e] && pos < g_off[e] + g_rows[e]);
    __half2 h0 = __floats2half2_rn(0.f, 0.f), h1 = h0;
    if (valid) {
        int t = g_perm[pos];
        float4 v = *reinterpret_cast<const float4*>(x + (size_t)t * DIM + threadIdx.x * 4);
        h0 = __floats2half2_rn(v.x, v.y);
        h1 = __floats2half2_rn(v.z, v.w);
    }
    __half2* dst = reinterpret_cast<__half2*>(g_X + (size_t)pos * DIM + threadIdx.x * 4);
    dst[0] = h0; dst[1] = h1;
}

// fp32 -> fp16 weight conversion (one-time per call, graph-safe)
__global__ void k_wconv(const float4* __restrict__ src, __half2* __restrict__ dst, int n4) {
    int i = blockIdx.x * blockDim.x + threadIdx.x;
    if (i >= n4) return;
    float4 v = src[i];
    dst[2*i]   = __floats2half2_rn(v.x, v.y);
    dst[2*i+1] = __floats2half2_rn(v.z, v.w);
}

__global__ void k_zero(float4* __restrict__ y) {
    y[blockIdx.x * 256 + threadIdx.x] = make_float4(0.f, 0.f, 0.f, 0.f);
}

__device__ __forceinline__ bool find_expert(int mt, int& e, int& m0, int& ne) {
    e = -1;
#pragma unroll
    for (int i = 0; i < NE; i++) {
        int o = g_off[i], r = g_rows[i];
        int t0 = o / BM, tl = (r + BM - 1) / BM;
        if (mt >= t0 && mt < t0 + tl) { e = i; m0 = o + (mt - t0) * BM; ne = o + r; }
    }
    return e >= 0;
}

// =============== GEMM 1+3 fused: H = silu(X@W1^T)*(X@W3^T), fp16 mma ===============
// CTA tile 128x64 (dual matrices), BK=32, 3-stage cp.async, 8 warps (2m x 4n).
// dyn smem halfs: A 3x(128*40) @0; B1 3x(64*40) @30720B; B3 @46080B. Total 61440B.
__global__ void __launch_bounds__(256, 2)
k_gemm13() {
    extern __shared__ __half sm13[];
    const uint32_t sbu = smem_u32(sm13);

    int e, m0, ne_;
    if (!find_expert((int)blockIdx.x, e, m0, ne_)) return;

    const int tid = threadIdx.x, lane = tid & 31, wid = tid >> 5;
    const int wm = wid & 1, wn = wid >> 1;
    const int n0 = blockIdx.y * 64;

    const __half* Ah  = g_X  + (size_t)m0 * DIM;
    const __half* B1h = g_W1h + ((size_t)e * DFFC + n0) * DIM;
    const __half* B3h = g_W3h + ((size_t)e * DFFC + n0) * DIM;

#define G13_LOAD(s, k0) do {                                                    \
    _Pragma("unroll")                                                           \
    for (int l = 0; l < 2; l++) {                                               \
        int idx = tid + l * 256, row = idx >> 2, q = idx & 3;                   \
        CPA(sbu + (uint32_t)((s)*10240 + row*80 + q*16),                        \
            Ah + (size_t)row * DIM + (k0) + q * 8);                             \
    }                                                                           \
    { int row = tid >> 2, q = tid & 3;                                          \
      CPA(sbu + (uint32_t)(30720 + (s)*5120 + row*80 + q*16),                   \
          B1h + (size_t)row * DIM + (k0) + q * 8);                              \
      CPA(sbu + (uint32_t)(46080 + (s)*5120 + row*80 + q*16),                   \
          B3h + (size_t)row * DIM + (k0) + q * 8); }                            \
    CPCOMMIT();                                                                 \
} while (0)

    const uint32_t aBase = sbu +
        (uint32_t)(((wm*64 + (lane & 15)) * HSTR + (lane >> 4) * 8) * 2);
    const uint32_t bRow = (uint32_t)(wn*16 + (lane & 7) + ((lane >> 4) & 1) * 8);
    const uint32_t bCol = (uint32_t)(((lane >> 3) & 1) * 8);
    const uint32_t b1Base = sbu + 30720u + (bRow * HSTR + bCol) * 2;
    const uint32_t b3Base = b1Base + 15360u;

    float c1[4][2][4], c3[4][2][4];
#pragma unroll
    for (int i = 0; i < 4; i++)
#pragma unroll
        for (int j = 0; j < 2; j++)
#pragma unroll
            for (int q = 0; q < 4; q++) { c1[i][j][q] = 0.f; c3[i][j][q] = 0.f; }

    const int NS = DIM / BK;   // 32
    G13_LOAD(0, 0);
    G13_LOAD(1, BK);

    for (int i = 0; i < NS; i++) {
        int s = i % 3;
        if (i + 1 < NS) CPWAIT(1); else CPWAIT(0);
        __syncthreads();
        if (i + 2 < NS) G13_LOAD((i + 2) % 3, (i + 2) * BK);

        uint32_t b1f[2][4], b3f[2][4];
#pragma unroll
        for (int ks = 0; ks < 2; ks++) {
            LDSM4(b1f[ks], b1Base + (uint32_t)(s*5120 + ks*32));
            LDSM4(b3f[ks], b3Base + (uint32_t)(s*5120 + ks*32));
        }
#pragma unroll
        for (int ks = 0; ks < 2; ks++) {
#pragma unroll
            for (int mt = 0; mt < 4; mt++) {
                uint32_t a[4];
                LDSM4(a, aBase + (uint32_t)(s*10240 + mt*1280 + ks*32));
                MMAH(c1[mt][0], a, b1f[ks][0], b1f[ks][1]);
                MMAH(c1[mt][1], a, b1f[ks][2], b1f[ks][3]);
                MMAH(c3[mt][0], a, b3f[ks][0], b3f[ks][1]);
                MMAH(c3[mt][1], a, b3f[ks][2], b3f[ks][3]);
            }
        }
    }

    // epilogue: h = silu(c1) * c3 -> fp16 -> g_H (pad rows compute exact 0)
#pragma unroll
    for (int mt = 0; mt < 4; mt++)
#pragma unroll
        for (int nj = 0; nj < 2; nj++) {
            int row = m0 + wm*64 + mt*16 + (lane >> 2);
            int col = n0 + wn*16 + nj*8 + (lane & 3) * 2;
#pragma unroll
            for (int h = 0; h < 2; h++) {
                int r = row + h * 8;
                float z0 = c1[mt][nj][h*2],   g0 = z0 / (1.f + __expf(-z0)) * c3[mt][nj][h*2];
                float z1 = c1[mt][nj][h*2+1], g1 = z1 / (1.f + __expf(-z1)) * c3[mt][nj][h*2+1];
                *reinterpret_cast<__half2*>(g_H + (size_t)r * DFFC + col) =
                    __floats2half2_rn(g0, g1);
            }
        }
}

// =============== GEMM 2: y += w * (H @ W2^T), fp16 mma ===============
// CTA tile 128x128, BK=32, 3-stage, 8 warps (2m x 4n), warp tile 64x32.
// dyn smem halfs: A 3x(128*40) @0; B 3x(128*40) @30720B. Total 61440B.
__global__ void __launch_bounds__(256, 2)
k_gemm2(float* __restrict__ y) {
    extern __shared__ __half sm2[];
    const uint32_t sbu = smem_u32(sm2);
    __shared__ int   srow[BM];
    __shared__ float swt[BM];

    int e, m0, ne_;
    if (!find_expert((int)blockIdx.y, e, m0, ne_)) return;

    const int tid = threadIdx.x, lane = tid & 31, wid = tid >> 5;
    const int wm = wid & 1, wn = wid >> 1;
    const int n0 = blockIdx.x * 128;

    if (tid < BM) {
        int pos = m0 + tid;
        bool v = pos < ne_;
        srow[tid] = v ? g_perm[pos] : -1;
        swt[tid]  = v ? g_pw[pos]   : 0.f;
    }

    const __half* Ah = g_H + (size_t)m0 * DFFC;
    const __half* Bh = g_W2h + ((size_t)e * DIM + n0) * DFFC;

#define G2_LOAD(s, k0) do {                                                     \
    _Pragma("unroll")                                                           \
    for (int l = 0; l < 2; l++) {                                               \
        int idx = tid + l * 256, row = idx >> 2, q = idx & 3;                   \
        CPA(sbu + (uint32_t)((s)*10240 + row*80 + q*16),                        \
            Ah + (size_t)row * DFFC + (k0) + q * 8);                            \
        CPA(sbu + (uint32_t)(30720 + (s)*10240 + row*80 + q*16),                \
            Bh + (size_t)row * DFFC + (k0) + q * 8);                            \
    }                                                                           \
    CPCOMMIT();                                                                 \
} while (0)

    const uint32_t aBase = sbu +
        (uint32_t)(((wm*64 + (lane & 15)) * HSTR + (lane >> 4) * 8) * 2);
    const uint32_t bRow = (uint32_t)(wn*32 + (lane & 7) + ((lane >> 4) & 1) * 8);
    const uint32_t bCol = (uint32_t)(((lane >> 3) & 1) * 8);
    const uint32_t bBase = sbu + 30720u + (bRow * HSTR + bCol) * 2;

    float c[4][4][4];
#pragma unroll
    for (int i = 0; i < 4; i++)
#pragma unroll
        for (int j = 0; j < 4; j++)
#pragma unroll
            for (int q = 0; q < 4; q++) c[i][j][q] = 0.f;

    const int NS = DFFC / BK;   // 128
    G2_LOAD(0, 0);
    G2_LOAD(1, BK);

    for (int i = 0; i < NS; i++) {
        int s = i % 3;
        if (i + 1 < NS) CPWAIT(1); else CPWAIT(0);
        __syncthreads();
        if (i + 2 < NS) G2_LOAD((i + 2) % 3, (i + 2) * BK);

        uint32_t bf[2][2][4];   // [nt][ks]
#pragma unroll
        for (int nt = 0; nt < 2; nt++)
#pragma unroll
            for (int ks = 0; ks < 2; ks++)
                LDSM4(bf[nt][ks], bBase + (uint32_t)(s*10240 + nt*1280 + ks*32));
#pragma unroll
        for (int ks = 0; ks < 2; ks++) {
#pragma unroll
            for (int mt = 0; mt < 4; mt++) {
                uint32_t a[4];
                LDSM4(a, aBase + (uint32_t)(s*10240 + mt*1280 + ks*32));
#pragma unroll
                for (int nt = 0; nt < 2; nt++) {
                    MMAH(c[mt][nt*2],   a, bf[nt][ks][0], bf[nt][ks][1]);
                    MMAH(c[mt][nt*2+1], a, bf[nt][ks][2], bf[nt][ks][3]);
                }
            }
        }
    }

    // epilogue: weighted scatter-add (2 commutative fp32 adds per output element)
#pragma unroll
    for (int mt = 0; mt < 4; mt++) {
        int rl = wm*64 + mt*16 + (lane >> 2);
#pragma unroll
        for (int h = 0; h < 2; h++) {
            int r = rl + h * 8;
            int t = srow[r];
            if (t >= 0) {
                float w = swt[r];
                float* yr = y + (size_t)t * DIM + n0 + wn*32 + (lane & 3) * 2;
#pragma unroll
                for (int nj = 0; nj < 4; nj++) {
                    atomicAdd(&yr[nj*8],     w * c[mt][nj][h*2]);
                    atomicAdd(&yr[nj*8 + 1], w * c[mt][nj][h*2+1]);
                }
            }
        }
    }
}

// ---------------- launch ----------------
#define SMEM_GEMM 61440

extern "C" void kernel_launch(void* const* d_in, const int* in_sizes, int n_in,
                              void* d_out, int out_size) {
    const float* x  = (const float*)d_in[0];
    const float* Wg = (const float*)d_in[1];
    const float* bg = (const float*)d_in[2];
    const float* W1 = (const float*)d_in[3];
    const float* W2 = (const float*)d_in[4];
    const float* W3 = (const float*)d_in[5];
    float* y = (float*)d_out;

    cudaFuncSetAttribute(k_gemm13, cudaFuncAttributeMaxDynamicSharedMemorySize, SMEM_GEMM);
    cudaFuncSetAttribute(k_gemm2,  cudaFuncAttributeMaxDynamicSharedMemorySize, SMEM_GEMM);

    // weight conversion (fp32 -> fp16)
    __half* w1h; cudaGetSymbolAddress((void**)&w1h, g_W1h);
    __half* w3h; cudaGetSymbolAddress((void**)&w3h, g_W3h);
    __half* w2h; cudaGetSymbolAddress((void**)&w2h, g_W2h);
    const int NW = NE * DFFC * DIM / 4;   // float4 count per weight tensor
    k_wconv<<<(NW + 255) / 256, 256>>>((const float4*)W1, (__half2*)w1h, NW);
    k_wconv<<<(NW + 255) / 256, 256>>>((const float4*)W3, (__half2*)w3h, NW);
    k_wconv<<<(NW + 255) / 256, 256>>>((const float4*)W2, (__half2*)w2h, NW);

    k_init<<<1, 32>>>();
    k_router<<<TOK / 4, 128>>>(x, Wg, bg);
    k_offsets<<<1, 1>>>();
    k_scatter<<<TOK / 256, 256>>>();
    k_gather<<<CAP, 256>>>(x);
    k_zero<<<(TOK * DIM) / 1024, 256>>>((float4*)y);

    dim3 g13(MT, DFFC / 64);           // x = m-tiles fast: W1/W3 panel L2 reuse
    k_gemm13<<<g13, 256, SMEM_GEMM>>>();
    dim3 g2(DIM / 128, MT);            // x = n (8): g_H tile L2 reuse
    k_gemm2<<<g2, 256, SMEM_GEMM>>>(y);
}